// round 9
// baseline (speedup 1.0000x reference)
#include <cuda_runtime.h>
#include <cstdint>

#define BB 8
#define FF 2048
#define LL 1024
#define THRESH 0.81f
#define BN_EPS 1e-5f

// scratch (device globals per allocation rules)
__device__ float g_h[BB * FF];     // raw pooled prelu means
__device__ float g_hbn[BB * FF];   // BN'd h
__device__ float g_dinv[BB * FF];  // rsqrt(degree)
__device__ unsigned int g_ctr;     // zero-initialized; reset by last block each run

// ---------------- k1: prelu + mean over L, BN fused into last block --------
// grid = BB*FF/8 = 2048 blocks, 256 threads = 8 warps. MLP=8 per lane.
__global__ void k1_rowmean_bn(const float* __restrict__ x,
                              const float* __restrict__ w1p,
                              const float* __restrict__ bw,
                              const float* __restrict__ bb) {
    const float w1 = w1p[0];
    const int warp = threadIdx.x >> 5, lane = threadIdx.x & 31;
    const int row = blockIdx.x * 8 + warp;
    const float4* xr = (const float4*)(x + (size_t)row * LL);

    float4 v[8];
    #pragma unroll
    for (int j = 0; j < 8; j++) v[j] = xr[lane + 32 * j];

    float s = 0.f;
    #pragma unroll
    for (int j = 0; j < 8; j++) {
        s += (v[j].x >= 0.f) ? v[j].x : w1 * v[j].x;
        s += (v[j].y >= 0.f) ? v[j].y : w1 * v[j].y;
        s += (v[j].z >= 0.f) ? v[j].z : w1 * v[j].z;
        s += (v[j].w >= 0.f) ? v[j].w : w1 * v[j].w;
    }
    #pragma unroll
    for (int o = 16; o; o >>= 1) s += __shfl_down_sync(0xffffffffu, s, o);
    if (lane == 0) g_h[row] = s * (1.0f / LL);

    // ---- last-block BN tail (replaces separate k2 launch) ----
    __shared__ bool is_last;
    __threadfence();                  // make g_h writes visible grid-wide
    __syncthreads();                  // all warps' g_h stores issued+fenced
    if (threadIdx.x == 0) {
        unsigned int old = atomicAdd(&g_ctr, 1u);
        is_last = (old == gridDim.x - 1);
        if (is_last) g_ctr = 0;       // reset for next graph replay
    }
    __syncthreads();
    if (!is_last) return;

    // this block alone: BN over batch for all channels (reads are L2 hits)
    #pragma unroll
    for (int c = 0; c < 8; c++) {
        const int f = threadIdx.x + c * 256;
        float vv[BB];
        float mu = 0.f;
        #pragma unroll
        for (int q = 0; q < BB; q++) { vv[q] = g_h[q * FF + f]; mu += vv[q]; }
        mu *= (1.0f / BB);
        float var = 0.f;
        #pragma unroll
        for (int q = 0; q < BB; q++) { float d = vv[q] - mu; var += d * d; }
        var *= (1.0f / BB);
        const float inv = rsqrtf(var + BN_EPS);
        const float w = bw[f], bi = bb[f];
        #pragma unroll
        for (int q = 0; q < BB; q++)
            g_hbn[q * FF + f] = (vv[q] - mu) * inv * w + bi;
    }
}

// ---------------- k3: degree + rsqrt (warp-per-row) ------------------------
// grid (FF/8, BB) = 2048 blocks, 256 threads = 8 warps.
__global__ void k3_deg() {
    const int b = blockIdx.y;
    __shared__ float4 sh4[FF / 4];
    const float4* hb4 = (const float4*)(g_hbn + b * FF);
    #pragma unroll
    for (int i = threadIdx.x; i < FF / 4; i += 256) sh4[i] = hb4[i];
    __syncthreads();

    const int warp = threadIdx.x >> 5, lane = threadIdx.x & 31;
    const int n = blockIdx.x * 8 + warp;
    const float hn = g_hbn[b * FF + n];  // uniform per warp -> broadcast
    float cnt = 0.f;
    #pragma unroll 4
    for (int i = lane; i < FF / 4; i += 32) {
        float4 v = sh4[i];
        // exact same FMUL-then-compare semantics as reference sim > THRESH
        cnt += (hn * v.x > THRESH) ? 1.f : 0.f;
        cnt += (hn * v.y > THRESH) ? 1.f : 0.f;
        cnt += (hn * v.z > THRESH) ? 1.f : 0.f;
        cnt += (hn * v.w > THRESH) ? 1.f : 0.f;
    }
    #pragma unroll
    for (int o = 16; o; o >>= 1) cnt += __shfl_down_sync(0xffffffffu, cnt, o);
    if (lane == 0) g_dinv[b * FF + n] = rsqrtf(cnt + 1.0f);  // +1 for identity
}

// ---------------- k4: expand output via smem staging + one-shot bulk TMA ----
// out[b,n,m] = dinv_n*dinv_m*[h_n*h_m > T] + (n==m)*dinv_n^2
// grid (FF/TILE_N, BB) = (512, 8) = 4096 blocks, 256 threads. 32KB tile,
// one cp.async.bulk store per block.
#define TILE_N 4
__global__ void k4_out(float* __restrict__ out) {
    __shared__ __align__(128) float tile[TILE_N * FF];  // 32 KB
    const int b = blockIdx.y;
    const int n0 = blockIdx.x * TILE_N;
    const float* __restrict__ hb = g_hbn + b * FF;
    const float* __restrict__ db = g_dinv + b * FF;

    // per-thread m columns: float4 indices q0 = tid, q1 = tid+256
    float hm[8], dm[8];
    #pragma unroll
    for (int j = 0; j < 2; j++) {
        const int q = threadIdx.x + j * 256;
        float4 h4 = ((const float4*)hb)[q];
        float4 d4 = ((const float4*)db)[q];
        hm[j * 4 + 0] = h4.x; hm[j * 4 + 1] = h4.y;
        hm[j * 4 + 2] = h4.z; hm[j * 4 + 3] = h4.w;
        dm[j * 4 + 0] = d4.x; dm[j * 4 + 1] = d4.y;
        dm[j * 4 + 2] = d4.z; dm[j * 4 + 3] = d4.w;
    }

    float4* t4 = (float4*)tile;
    #pragma unroll
    for (int nn = 0; nn < TILE_N; nn++) {
        const int n = n0 + nn;
        const float hn = hb[n];        // uniform -> broadcast, L1 hit
        const float dn = db[n];
        const float diag = dn * dn;
        #pragma unroll
        for (int j = 0; j < 2; j++) {
            const int q = threadIdx.x + j * 256;
            const int mg = q * 4;
            float4 r;
            float* rp = &r.x;
            #pragma unroll
            for (int k = 0; k < 4; k++) {
                float v = (hn * hm[j * 4 + k] > THRESH) ? dn * dm[j * 4 + k] : 0.f;
                if (mg + k == n) v += diag;
                rp[k] = v;
            }
            t4[nn * (FF / 4) + q] = r;
        }
    }
    __syncthreads();

    if (threadIdx.x == 0) {
        asm volatile("fence.proxy.async.shared::cta;" ::: "memory");
        uint32_t saddr;
        asm("{ .reg .u64 t; cvta.to.shared.u64 t, %1; cvt.u32.u64 %0, t; }"
            : "=r"(saddr) : "l"(tile));
        float* gdst = out + (size_t)b * FF * FF + (size_t)n0 * FF;
        const unsigned bytes = TILE_N * FF * 4;  // 32768
        asm volatile(
            "cp.async.bulk.global.shared::cta.bulk_group [%0], [%1], %2;"
            :: "l"(gdst), "r"(saddr), "r"(bytes) : "memory");
        asm volatile("cp.async.bulk.commit_group;" ::: "memory");
        asm volatile("cp.async.bulk.wait_group.read 0;" ::: "memory");
    }
}

extern "C" void kernel_launch(void* const* d_in, const int* in_sizes, int n_in,
                              void* d_out, int out_size) {
    const float* x   = (const float*)d_in[0];
    const float* w1  = (const float*)d_in[1];
    // d_in[2] = prelu2_w: unused — A_hat is provably nonnegative, PReLU is identity
    const float* bnw = (const float*)d_in[3];
    const float* bnb = (const float*)d_in[4];
    float* out = (float*)d_out;

    k1_rowmean_bn<<<BB * FF / 8, 256>>>(x, w1, bnw, bnb);
    k3_deg<<<dim3(FF / 8, BB), 256>>>();
    k4_out<<<dim3(FF / TILE_N, BB), 256>>>(out);
}

// round 10
// speedup vs baseline: 1.1317x; 1.1317x over previous
#include <cuda_runtime.h>
#include <cstdint>

#define BB 8
#define FF 2048
#define LL 1024
#define THRESH 0.81f
#define BN_EPS 1e-5f

// scratch (device globals per allocation rules)
__device__ float g_h[BB * FF];     // raw pooled prelu means (k1 output)
__device__ float g_hbn[BB * FF];   // BN'd h (k23 output)
__device__ float g_dinv[BB * FF];  // rsqrt(degree)

// ---------------- k1: prelu + mean over L (warp-per-row) ----------------
// grid = BB*FF/8 = 2048 blocks, 256 threads = 8 warps. MLP=8 per lane.
// (measured-best: 13.5us, near DRAM-read floor at DVFS clocks)
__global__ void k1_rowmean(const float* __restrict__ x,
                           const float* __restrict__ w1p) {
    const float w1 = w1p[0];
    const int warp = threadIdx.x >> 5, lane = threadIdx.x & 31;
    const int row = blockIdx.x * 8 + warp;
    const float4* xr = (const float4*)(x + (size_t)row * LL);

    float4 v[8];
    #pragma unroll
    for (int j = 0; j < 8; j++) v[j] = xr[lane + 32 * j];

    float s = 0.f;
    #pragma unroll
    for (int j = 0; j < 8; j++) {
        s += (v[j].x >= 0.f) ? v[j].x : w1 * v[j].x;
        s += (v[j].y >= 0.f) ? v[j].y : w1 * v[j].y;
        s += (v[j].z >= 0.f) ? v[j].z : w1 * v[j].z;
        s += (v[j].w >= 0.f) ? v[j].w : w1 * v[j].w;
    }
    #pragma unroll
    for (int o = 16; o; o >>= 1) s += __shfl_down_sync(0xffffffffu, s, o);
    if (lane == 0) g_h[row] = s * (1.0f / LL);
}

// ---------------- k23_v2: fused BatchNorm + degree ----------------
// grid (FF/32, BB) = (64, 8) = 512 blocks, 512 threads = 16 warps.
// Each block redundantly computes BN for ALL channels of batch b into smem
// (coalesced L2-hit loads), writes its 32-column slice of g_hbn, then warp w
// counts degree for rows bx*32 + w*2 .. +1 against smem.
#define SLICE 32
__global__ void k23_bn_deg(const float* __restrict__ bw,
                           const float* __restrict__ bb) {
    const int b = blockIdx.y;
    __shared__ float sh[FF];
    const int tid = threadIdx.x;

    // BN: 4 channels per thread (coalesced, f = tid + c*512)
    #pragma unroll
    for (int c = 0; c < 4; c++) {
        const int f = tid + c * 512;
        float v[BB];
        float mu = 0.f;
        #pragma unroll
        for (int q = 0; q < BB; q++) { v[q] = g_h[q * FF + f]; mu += v[q]; }
        mu *= (1.0f / BB);
        float var = 0.f;
        #pragma unroll
        for (int q = 0; q < BB; q++) { float d = v[q] - mu; var += d * d; }
        var *= (1.0f / BB);
        const float hv = (v[b] - mu) * rsqrtf(var + BN_EPS) * bw[f] + bb[f];
        sh[f] = hv;
        if ((f >> 5) == (int)blockIdx.x) g_hbn[b * FF + f] = hv;
    }
    __syncthreads();

    // degree count: warp w -> 2 rows
    const int warp = tid >> 5, lane = tid & 31;
    const int nbase = blockIdx.x * SLICE + warp * 2;
    float hn0 = sh[nbase], hn1 = sh[nbase + 1];
    float c0 = 0.f, c1 = 0.f;

    const float4* s4 = (const float4*)sh;
    #pragma unroll 4
    for (int i = lane; i < FF / 4; i += 32) {
        float4 v = s4[i];
        c0 += (hn0 * v.x > THRESH) ? 1.f : 0.f;
        c0 += (hn0 * v.y > THRESH) ? 1.f : 0.f;
        c0 += (hn0 * v.z > THRESH) ? 1.f : 0.f;
        c0 += (hn0 * v.w > THRESH) ? 1.f : 0.f;
        c1 += (hn1 * v.x > THRESH) ? 1.f : 0.f;
        c1 += (hn1 * v.y > THRESH) ? 1.f : 0.f;
        c1 += (hn1 * v.z > THRESH) ? 1.f : 0.f;
        c1 += (hn1 * v.w > THRESH) ? 1.f : 0.f;
    }
    #pragma unroll
    for (int o = 16; o; o >>= 1) {
        c0 += __shfl_down_sync(0xffffffffu, c0, o);
        c1 += __shfl_down_sync(0xffffffffu, c1, o);
    }
    if (lane == 0) {
        g_dinv[b * FF + nbase]     = rsqrtf(c0 + 1.0f);  // +1 identity
        g_dinv[b * FF + nbase + 1] = rsqrtf(c1 + 1.0f);
    }
}

// ---------------- k4: expand output, split-commit bulk TMA ------------------
// out[b,n,m] = dinv_n*dinv_m*[h_n*h_m > T] + (n==m)*dinv_n^2
// grid (FF/4, BB) = (512, 8) = 4096 blocks, 256 threads. Two 16KB buffers,
// each committed as its own bulk group; buf0's TMA read overlaps buf1 compute.
#define TILE_N 4
__global__ void k4_out(float* __restrict__ out) {
    __shared__ __align__(128) float tile[2][(TILE_N / 2) * FF];  // 2 x 16 KB
    const int b = blockIdx.y;
    const int n0 = blockIdx.x * TILE_N;
    const float* __restrict__ hb = g_hbn + b * FF;
    const float* __restrict__ db = g_dinv + b * FF;

    // per-thread m columns: float4 indices q0 = tid, q1 = tid+256
    float hm[8], dm[8];
    #pragma unroll
    for (int j = 0; j < 2; j++) {
        const int q = threadIdx.x + j * 256;
        float4 h4 = ((const float4*)hb)[q];
        float4 d4 = ((const float4*)db)[q];
        hm[j * 4 + 0] = h4.x; hm[j * 4 + 1] = h4.y;
        hm[j * 4 + 2] = h4.z; hm[j * 4 + 3] = h4.w;
        dm[j * 4 + 0] = d4.x; dm[j * 4 + 1] = d4.y;
        dm[j * 4 + 2] = d4.z; dm[j * 4 + 3] = d4.w;
    }

    uint32_t sbase;
    asm("{ .reg .u64 t; cvta.to.shared.u64 t, %1; cvt.u32.u64 %0, t; }"
        : "=r"(sbase) : "l"(&tile[0][0]));
    float* outb = out + (size_t)b * FF * FF;

    #pragma unroll
    for (int half = 0; half < 2; half++) {
        float4* t4 = (float4*)tile[half];
        #pragma unroll
        for (int nn = 0; nn < 2; nn++) {
            const int n = n0 + half * 2 + nn;
            const float hn = hb[n];        // uniform -> broadcast, L1 hit
            const float dn = db[n];
            const float diag = dn * dn;
            #pragma unroll
            for (int j = 0; j < 2; j++) {
                const int q = threadIdx.x + j * 256;
                const int mg = q * 4;
                float4 r;
                float* rp = &r.x;
                #pragma unroll
                for (int k = 0; k < 4; k++) {
                    float v = (hn * hm[j * 4 + k] > THRESH) ? dn * dm[j * 4 + k]
                                                            : 0.f;
                    if (mg + k == n) v += diag;
                    rp[k] = v;
                }
                t4[nn * (FF / 4) + q] = r;
            }
        }
        __syncthreads();
        if (threadIdx.x == 0) {
            asm volatile("fence.proxy.async.shared::cta;" ::: "memory");
            float* gdst = outb + (size_t)(n0 + half * 2) * FF;
            const unsigned bytes = 2 * FF * 4;  // 16384
            asm volatile(
                "cp.async.bulk.global.shared::cta.bulk_group [%0], [%1], %2;"
                :: "l"(gdst), "r"(sbase + half * (2 * FF * 4)), "r"(bytes)
                : "memory");
            asm volatile("cp.async.bulk.commit_group;" ::: "memory");
        }
    }
    // final drain: keep CTA alive until both bulk reads of smem complete
    if (threadIdx.x == 0)
        asm volatile("cp.async.bulk.wait_group.read 0;" ::: "memory");
    __syncthreads();
}

extern "C" void kernel_launch(void* const* d_in, const int* in_sizes, int n_in,
                              void* d_out, int out_size) {
    const float* x   = (const float*)d_in[0];
    const float* w1  = (const float*)d_in[1];
    // d_in[2] = prelu2_w: unused — A_hat is provably nonnegative, PReLU is identity
    const float* bnw = (const float*)d_in[3];
    const float* bnb = (const float*)d_in[4];
    float* out = (float*)d_out;

    k1_rowmean<<<BB * FF / 8, 256>>>(x, w1);
    k23_bn_deg<<<dim3(FF / SLICE, BB), 512>>>(bnw, bnb);
    k4_out<<<dim3(FF / TILE_N, BB), 256>>>(out);
}